// round 2
// baseline (speedup 1.0000x reference)
#include <cuda_runtime.h>
#include <cuda_bf16.h>
#include <math.h>

#define TT 128
#define BB 32
#define HH 1024
#define VV 32000
#define NROWS (TT*BB)          // 4096
#define NLAYERS 2

// ---------------- scratch (no allocations allowed) ----------------
__device__ float g_bufA[NROWS * HH];
__device__ float g_bufB[NROWS * HH];
__device__ float g_bufC[NROWS * HH];
__device__ float g_lse[NROWS];

// ---------------- helpers ----------------
__device__ __forceinline__ unsigned f2tf(float x) {
    unsigned r;
    asm("cvt.rna.tf32.f32 %0, %1;" : "=r"(r) : "f"(x));
    return r;
}

__device__ __forceinline__ void mma_tf32(float* c, const unsigned* a, const unsigned* b) {
    asm volatile(
        "mma.sync.aligned.m16n8k8.row.col.f32.tf32.tf32.f32 "
        "{%0,%1,%2,%3}, {%4,%5,%6,%7}, {%8,%9}, {%0,%1,%2,%3};\n"
        : "+f"(c[0]), "+f"(c[1]), "+f"(c[2]), "+f"(c[3])
        : "r"(a[0]), "r"(a[1]), "r"(a[2]), "r"(a[3]), "r"(b[0]), "r"(b[1]));
}

// ---------------- embedding gather ----------------
__global__ void embed_kernel(const int* __restrict__ idx, const float* __restrict__ emb,
                             float* __restrict__ out) {
    int r = blockIdx.x;
    int token = idx[r];
    const float4* src = (const float4*)(emb + (size_t)token * HH);
    float4* dst = (float4*)(out + (size_t)r * HH);
    for (int c = threadIdx.x; c < HH / 4; c += blockDim.x) dst[c] = src[c];
}

// ---------------- tf32 tensor-core GEMM: C[M,N] = A[M,K] @ W[N,K]^T + bias ----------------
#define GBM 128
#define GBN 64
#define GBK 32
#define GPAD 4

__global__ __launch_bounds__(256) void gemm_tf32(
    const float* __restrict__ A, const float* __restrict__ W, const float* __restrict__ bias,
    float* __restrict__ C, int M, int N, int K) {
    __shared__ unsigned As[GBM][GBK + GPAD];
    __shared__ unsigned Bs[GBN][GBK + GPAD];

    const int tid = threadIdx.x;
    const int lane = tid & 31;
    const int wid = tid >> 5;                 // 0..7
    const int wm = (wid & 3) * 32;            // warp m offset (4 warps in m)
    const int wn = (wid >> 2) * 32;           // warp n offset (2 warps in n)
    const int bm = blockIdx.y * GBM;
    const int bn = blockIdx.x * GBN;
    const int gr = lane >> 2;                 // group row 0..7
    const int gc = lane & 3;                  // group col 0..3

    float acc[2][4][4];
#pragma unroll
    for (int mt = 0; mt < 2; mt++)
#pragma unroll
        for (int nt = 0; nt < 4; nt++)
#pragma unroll
            for (int i = 0; i < 4; i++) acc[mt][nt][i] = 0.f;

    for (int k0 = 0; k0 < K; k0 += GBK) {
        // load A tile 128x32 (4 float4 per thread)
#pragma unroll
        for (int i = 0; i < 4; i++) {
            int lin = tid + i * 256;
            int r = lin >> 3;
            int c4 = (lin & 7) * 4;
            float4 v = *(const float4*)(A + (size_t)(bm + r) * K + k0 + c4);
            As[r][c4 + 0] = f2tf(v.x);
            As[r][c4 + 1] = f2tf(v.y);
            As[r][c4 + 2] = f2tf(v.z);
            As[r][c4 + 3] = f2tf(v.w);
        }
        // load B (weights) tile 64x32 (2 float4 per thread)
#pragma unroll
        for (int i = 0; i < 2; i++) {
            int lin = tid + i * 256;
            int r = lin >> 3;
            int c4 = (lin & 7) * 4;
            float4 v = *(const float4*)(W + (size_t)(bn + r) * K + k0 + c4);
            Bs[r][c4 + 0] = f2tf(v.x);
            Bs[r][c4 + 1] = f2tf(v.y);
            Bs[r][c4 + 2] = f2tf(v.z);
            Bs[r][c4 + 3] = f2tf(v.w);
        }
        __syncthreads();

#pragma unroll
        for (int kk = 0; kk < GBK; kk += 8) {
            unsigned a[2][4];
#pragma unroll
            for (int mt = 0; mt < 2; mt++) {
                int mr = wm + mt * 16 + gr;
                a[mt][0] = As[mr][kk + gc];
                a[mt][1] = As[mr + 8][kk + gc];
                a[mt][2] = As[mr][kk + gc + 4];
                a[mt][3] = As[mr + 8][kk + gc + 4];
            }
            unsigned b[4][2];
#pragma unroll
            for (int nt = 0; nt < 4; nt++) {
                int nr = wn + nt * 8 + gr;
                b[nt][0] = Bs[nr][kk + gc];
                b[nt][1] = Bs[nr][kk + gc + 4];
            }
#pragma unroll
            for (int mt = 0; mt < 2; mt++)
#pragma unroll
                for (int nt = 0; nt < 4; nt++) mma_tf32(acc[mt][nt], a[mt], b[nt]);
        }
        __syncthreads();
    }

    // epilogue: + bias, store fp32
#pragma unroll
    for (int mt = 0; mt < 2; mt++) {
#pragma unroll
        for (int nt = 0; nt < 4; nt++) {
            int row = bm + wm + mt * 16 + gr;
            int col = bn + wn + nt * 8 + gc * 2;
            float b0 = bias ? bias[col] : 0.f;
            float b1 = bias ? bias[col + 1] : 0.f;
            C[(size_t)row * N + col]         = acc[mt][nt][0] + b0;
            C[(size_t)row * N + col + 1]     = acc[mt][nt][1] + b1;
            C[(size_t)(row + 8) * N + col]   = acc[mt][nt][2] + b0;
            C[(size_t)(row + 8) * N + col + 1] = acc[mt][nt][3] + b1;
        }
    }
}

// ---------------- one RNN timestep: h_t = tanh(pre_t + h_{t-1} @ Wh^T + bh) ----------------
// grid: 128 blocks (8 output cols each), 256 threads: thread = (b = tid&31, j = tid>>5)
__global__ __launch_bounds__(256) void rnn_step(
    const float* __restrict__ pre, float* __restrict__ ys, const float* __restrict__ h0,
    const float* __restrict__ Wh, const float* __restrict__ bh, int t) {
    __shared__ float hs[128 * 33];   // [k][b], padded
    __shared__ float ws[8 * 128];    // [j][k]

    const float* hprev = (t == 0) ? h0 : (ys + (size_t)(t - 1) * BB * HH);
    const int tid = threadIdx.x;
    const int b = tid & 31;
    const int j = tid >> 5;
    const int j0 = blockIdx.x * 8;
    const float* wsj = ws + j * 128;

    float a0 = 0.f, a1 = 0.f, a2 = 0.f, a3 = 0.f;

    for (int kc = 0; kc < HH; kc += 128) {
        // stage h chunk transposed: hs[k][b]
#pragma unroll
        for (int i = 0; i < 4; i++) {
            int lin = tid + i * 256;
            int r = lin >> 5;           // batch row 0..31
            int c4 = (lin & 31) * 4;    // k within chunk
            float4 v = *(const float4*)(hprev + (size_t)r * HH + kc + c4);
            hs[(c4 + 0) * 33 + r] = v.x;
            hs[(c4 + 1) * 33 + r] = v.y;
            hs[(c4 + 2) * 33 + r] = v.z;
            hs[(c4 + 3) * 33 + r] = v.w;
        }
        // stage W chunk: ws[j][k]
        {
            int jj = tid >> 5;
            int c4 = (tid & 31) * 4;
            float4 v = *(const float4*)(Wh + (size_t)(j0 + jj) * HH + kc + c4);
            ws[jj * 128 + c4 + 0] = v.x;
            ws[jj * 128 + c4 + 1] = v.y;
            ws[jj * 128 + c4 + 2] = v.z;
            ws[jj * 128 + c4 + 3] = v.w;
        }
        __syncthreads();

#pragma unroll 16
        for (int k = 0; k < 128; k += 4) {
            a0 = fmaf(hs[(k + 0) * 33 + b], wsj[k + 0], a0);
            a1 = fmaf(hs[(k + 1) * 33 + b], wsj[k + 1], a1);
            a2 = fmaf(hs[(k + 2) * 33 + b], wsj[k + 2], a2);
            a3 = fmaf(hs[(k + 3) * 33 + b], wsj[k + 3], a3);
        }
        __syncthreads();
    }

    int col = j0 + j;
    size_t row = (size_t)t * BB + b;
    float v = tanhf(((a0 + a1) + (a2 + a3)) + pre[row * HH + col] + bh[col]);
    ys[row * HH + col] = v;
}

// ---------------- online logsumexp per row ----------------
__global__ void lse_kernel(const float* __restrict__ logits, float* __restrict__ lse) {
    int r = blockIdx.x;
    int tid = threadIdx.x;
    const float* row = logits + (size_t)r * VV;
    float m = -1e30f, s = 0.f;
    for (int i = tid; i < VV; i += 256) {
        float x = row[i];
        if (x > m) { s = s * __expf(m - x) + 1.f; m = x; }
        else       { s += __expf(x - m); }
    }
    __shared__ float sm[256], ss[256];
    sm[tid] = m; ss[tid] = s;
    __syncthreads();
    for (int st = 128; st > 0; st >>= 1) {
        if (tid < st) {
            float m2 = sm[tid + st], s2 = ss[tid + st];
            float M = fmaxf(sm[tid], m2);
            ss[tid] = ss[tid] * __expf(sm[tid] - M) + s2 * __expf(m2 - M);
            sm[tid] = M;
        }
        __syncthreads();
    }
    if (tid == 0) lse[r] = sm[0] + logf(ss[0]);
}

__global__ void norm_kernel(float* __restrict__ out, const float* __restrict__ lse) {
    int r = blockIdx.y;
    int c = blockIdx.x * 256 + threadIdx.x;   // grid.x = 125 -> 32000 cols
    out[(size_t)r * VV + c] -= lse[r];
}

__global__ void hid_kernel(const float* __restrict__ ys0, const float* __restrict__ ys1,
                           float* __restrict__ out) {
    int i = blockIdx.x * 256 + threadIdx.x;   // 65536
    int l = i >> 15;
    int rem = i & 32767;                       // b*H + h
    const float* src = l ? ys1 : ys0;
    out[i] = src[(size_t)(TT - 1) * BB * HH + rem];
}

// ---------------- launch ----------------
extern "C" void kernel_launch(void* const* d_in, const int* in_sizes, int n_in,
                              void* d_out, int out_size) {
    const int*   input_x = (const int*)d_in[0];
    const float* hidden  = (const float*)d_in[1];
    const float* emb     = (const float*)d_in[2];
    const float* W_ih    = (const float*)d_in[3];
    const float* W_hh    = (const float*)d_in[4];
    const float* b_ih    = (const float*)d_in[5];
    const float* b_hh    = (const float*)d_in[6];
    const float* W_out   = (const float*)d_in[7];
    const float* b_out   = (const float*)d_in[8];
    float* out = (float*)d_out;

    float *bufA, *bufB, *bufC, *lse;
    cudaGetSymbolAddress((void**)&bufA, g_bufA);
    cudaGetSymbolAddress((void**)&bufB, g_bufB);
    cudaGetSymbolAddress((void**)&bufC, g_bufC);
    cudaGetSymbolAddress((void**)&lse,  g_lse);

    // x = emb[input]  -> bufA [4096,1024]
    embed_kernel<<<NROWS, 256>>>(input_x, emb, bufA);

    // layer 0: pre = x @ Wih0^T + bih0 -> bufB
    gemm_tf32<<<dim3(HH / GBN, NROWS / GBM), 256>>>(bufA, W_ih, b_ih, bufB, NROWS, HH, HH);
    for (int t = 0; t < TT; t++)
        rnn_step<<<HH / 8, 256>>>(bufB, bufC, hidden, W_hh, b_hh, t);

    // layer 1: pre = ys0 @ Wih1^T + bih1 -> bufB
    gemm_tf32<<<dim3(HH / GBN, NROWS / GBM), 256>>>(bufC, W_ih + (size_t)HH * HH, b_ih + HH,
                                                    bufB, NROWS, HH, HH);
    for (int t = 0; t < TT; t++)
        rnn_step<<<HH / 8, 256>>>(bufB, bufA, hidden + BB * HH,
                                  W_hh + (size_t)HH * HH, b_hh + HH, t);

    // logits = ys1 @ W_out^T + b_out -> d_out (in place, then normalized)
    gemm_tf32<<<dim3(VV / GBN, NROWS / GBM), 256>>>(bufA, W_out, b_out, out, NROWS, VV, HH);

    lse_kernel<<<NROWS, 256>>>(out, lse);
    norm_kernel<<<dim3(VV / 256, NROWS), 256>>>(out, lse);

    if (out_size >= NROWS * VV + NLAYERS * BB * HH)
        hid_kernel<<<(NLAYERS * BB * HH) / 256, 256>>>(bufC, bufA, out + (size_t)NROWS * VV);
}

// round 4
// speedup vs baseline: 1.3077x; 1.3077x over previous
#include <cuda_runtime.h>
#include <cuda_bf16.h>
#include <math.h>

#define TT 128
#define BB 32
#define HH 1024
#define VV 32000
#define NROWS (TT*BB)          // 4096
#define NLAYERS 2

#define RNN_BLOCKS 128
#define COLS_PER_BLK 8
#define CHUNK_K 256
#define NCHUNK (HH / CHUNK_K)
#define HROW 260               // 256 + 4 pad floats (16B) -> conflict-free float4 LDS
#define WS_FLOATS (COLS_PER_BLK * HH)           // 8192
#define BUF_FLOATS (BB * HROW)                  // 8320
#define RNN_SMEM_BYTES ((WS_FLOATS + 2 * BUF_FLOATS) * 4)   // 99,328 B

// ---------------- scratch (no allocations allowed) ----------------
__device__ float g_bufA[NROWS * HH];
__device__ float g_bufB[NROWS * HH];
__device__ float g_bufC[NROWS * HH];
__device__ float g_lse[NROWS];
__device__ unsigned g_bar;
__device__ volatile unsigned g_gen;

// ---------------- helpers ----------------
__device__ __forceinline__ unsigned f2tf(float x) {
    unsigned r;
    asm("cvt.rna.tf32.f32 %0, %1;" : "=r"(r) : "f"(x));
    return r;
}

__device__ __forceinline__ void mma_tf32(float* c, const unsigned* a, const unsigned* b) {
    asm volatile(
        "mma.sync.aligned.m16n8k8.row.col.f32.tf32.tf32.f32 "
        "{%0,%1,%2,%3}, {%4,%5,%6,%7}, {%8,%9}, {%0,%1,%2,%3};\n"
        : "+f"(c[0]), "+f"(c[1]), "+f"(c[2]), "+f"(c[3])
        : "r"(a[0]), "r"(a[1]), "r"(a[2]), "r"(a[3]), "r"(b[0]), "r"(b[1]));
}

__device__ __forceinline__ void cp_async16(void* smem_dst, const void* gsrc) {
    unsigned s = (unsigned)__cvta_generic_to_shared(smem_dst);
    asm volatile("cp.async.ca.shared.global [%0], [%1], 16;" :: "r"(s), "l"(gsrc));
}
__device__ __forceinline__ void cp_commit() {
    asm volatile("cp.async.commit_group;");
}
template <int N>
__device__ __forceinline__ void cp_wait() {
    asm volatile("cp.async.wait_group %0;" :: "n"(N));
}

// ---------------- embedding gather ----------------
__global__ void embed_kernel(const int* __restrict__ idx, const float* __restrict__ emb,
                             float* __restrict__ out) {
    int r = blockIdx.x;
    int token = idx[r];
    const float4* src = (const float4*)(emb + (size_t)token * HH);
    float4* dst = (float4*)(out + (size_t)r * HH);
    for (int c = threadIdx.x; c < HH / 4; c += blockDim.x) dst[c] = src[c];
}

// ---------------- tf32 tensor-core GEMM: C[M,N] = A[M,K] @ W[N,K]^T + bias ----------------
#define GBM 128
#define GBN 64
#define GBK 32
#define GPAD 4

__global__ __launch_bounds__(256) void gemm_tf32(
    const float* __restrict__ A, const float* __restrict__ W, const float* __restrict__ bias,
    float* __restrict__ C, int M, int N, int K) {
    __shared__ unsigned As[GBM][GBK + GPAD];
    __shared__ unsigned Bs[GBN][GBK + GPAD];

    const int tid = threadIdx.x;
    const int lane = tid & 31;
    const int wid = tid >> 5;
    const int wm = (wid & 3) * 32;
    const int wn = (wid >> 2) * 32;
    const int bm = blockIdx.y * GBM;
    const int bn = blockIdx.x * GBN;
    const int gr = lane >> 2;
    const int gc = lane & 3;

    float acc[2][4][4];
#pragma unroll
    for (int mt = 0; mt < 2; mt++)
#pragma unroll
        for (int nt = 0; nt < 4; nt++)
#pragma unroll
            for (int i = 0; i < 4; i++) acc[mt][nt][i] = 0.f;

    for (int k0 = 0; k0 < K; k0 += GBK) {
#pragma unroll
        for (int i = 0; i < 4; i++) {
            int lin = tid + i * 256;
            int r = lin >> 3;
            int c4 = (lin & 7) * 4;
            float4 v = *(const float4*)(A + (size_t)(bm + r) * K + k0 + c4);
            As[r][c4 + 0] = f2tf(v.x);
            As[r][c4 + 1] = f2tf(v.y);
            As[r][c4 + 2] = f2tf(v.z);
            As[r][c4 + 3] = f2tf(v.w);
        }
#pragma unroll
        for (int i = 0; i < 2; i++) {
            int lin = tid + i * 256;
            int r = lin >> 3;
            int c4 = (lin & 7) * 4;
            float4 v = *(const float4*)(W + (size_t)(bn + r) * K + k0 + c4);
            Bs[r][c4 + 0] = f2tf(v.x);
            Bs[r][c4 + 1] = f2tf(v.y);
            Bs[r][c4 + 2] = f2tf(v.z);
            Bs[r][c4 + 3] = f2tf(v.w);
        }
        __syncthreads();

#pragma unroll
        for (int kk = 0; kk < GBK; kk += 8) {
            unsigned a[2][4];
#pragma unroll
            for (int mt = 0; mt < 2; mt++) {
                int mr = wm + mt * 16 + gr;
                a[mt][0] = As[mr][kk + gc];
                a[mt][1] = As[mr + 8][kk + gc];
                a[mt][2] = As[mr][kk + gc + 4];
                a[mt][3] = As[mr + 8][kk + gc + 4];
            }
            unsigned b[4][2];
#pragma unroll
            for (int nt = 0; nt < 4; nt++) {
                int nr = wn + nt * 8 + gr;
                b[nt][0] = Bs[nr][kk + gc];
                b[nt][1] = Bs[nr][kk + gc + 4];
            }
#pragma unroll
            for (int mt = 0; mt < 2; mt++)
#pragma unroll
                for (int nt = 0; nt < 4; nt++) mma_tf32(acc[mt][nt], a[mt], b[nt]);
        }
        __syncthreads();
    }

#pragma unroll
    for (int mt = 0; mt < 2; mt++) {
#pragma unroll
        for (int nt = 0; nt < 4; nt++) {
            int row = bm + wm + mt * 16 + gr;
            int col = bn + wn + nt * 8 + gc * 2;
            float b0 = bias ? bias[col] : 0.f;
            float b1 = bias ? bias[col + 1] : 0.f;
            C[(size_t)row * N + col]           = acc[mt][nt][0] + b0;
            C[(size_t)row * N + col + 1]       = acc[mt][nt][1] + b1;
            C[(size_t)(row + 8) * N + col]     = acc[mt][nt][2] + b0;
            C[(size_t)(row + 8) * N + col + 1] = acc[mt][nt][3] + b1;
        }
    }
}

// ---------------- barrier reset ----------------
__global__ void reset_bar_kernel() {
    g_bar = 0;
    g_gen = 0;
}

// ---------------- grid barrier (all 128 blocks co-resident) ----------------
__device__ __forceinline__ void grid_barrier(unsigned target) {
    __syncthreads();
    if (threadIdx.x == 0) {
        __threadfence();
        unsigned old = atomicAdd(&g_bar, 1);
        if (old == RNN_BLOCKS - 1) {
            g_bar = 0;
            __threadfence();
            g_gen = target;
        } else {
            while (g_gen < target) {}
        }
        __threadfence();
    }
    __syncthreads();
}

// ---------------- persistent RNN layer ----------------
// grid = 128 blocks x 256 threads; block owns cols [8*bx, 8*bx+8)
// thread = (b = tid&31, j = tid>>5); W slice resident in smem all 128 steps.
__global__ __launch_bounds__(256) void persistent_rnn(
    const float* __restrict__ pre, float* __restrict__ ys, const float* __restrict__ h0,
    const float* __restrict__ Wh, const float* __restrict__ bh) {
    extern __shared__ float smem[];
    float* ws   = smem;                       // [8][1024]
    float* bufs = smem + WS_FLOATS;           // 2 x [32][260]

    const int tid = threadIdx.x;
    const int b = tid & 31;
    const int j = tid >> 5;
    const int j0 = blockIdx.x * COLS_PER_BLK;
    const int col = j0 + j;

    // load W slice (8 x 1024 floats = 2048 float4) once
    {
        const float4* wsrc = (const float4*)(Wh + (size_t)j0 * HH);
        float4* wdst = (float4*)ws;
#pragma unroll
        for (int i = 0; i < 8; i++) wdst[tid + i * 256] = wsrc[tid + i * 256];
    }
    const float bj = bh[col];
    __syncthreads();

    for (int t = 0; t < TT; t++) {
        const float* hprev = (t == 0) ? h0 : (ys + (size_t)(t - 1) * BB * HH);
        if (t) grid_barrier((unsigned)t);

        // prologue: issue chunk 0
        {
            const float* src = hprev;
            float* dst = bufs;
#pragma unroll
            for (int i = 0; i < 8; i++) {
                int lin = tid + i * 256;
                int row = lin >> 6;
                int seg = lin & 63;
                cp_async16(dst + row * HROW + seg * 4, src + row * HH + seg * 4);
            }
            cp_commit();
        }

        float a0 = 0.f, a1 = 0.f, a2 = 0.f, a3 = 0.f;

#pragma unroll
        for (int c = 0; c < NCHUNK; c++) {
            if (c + 1 < NCHUNK) {
                const float* src = hprev + (c + 1) * CHUNK_K;
                float* dst = bufs + ((c + 1) & 1) * BUF_FLOATS;
#pragma unroll
                for (int i = 0; i < 8; i++) {
                    int lin = tid + i * 256;
                    int row = lin >> 6;
                    int seg = lin & 63;
                    cp_async16(dst + row * HROW + seg * 4, src + row * HH + seg * 4);
                }
                cp_commit();
                cp_wait<1>();
            } else {
                cp_wait<0>();
            }
            __syncthreads();

            const float* hb = bufs + (c & 1) * BUF_FLOATS + b * HROW;
            const float* wj = ws + j * HH + c * CHUNK_K;
#pragma unroll 8
            for (int kk = 0; kk < CHUNK_K; kk += 4) {
                float4 h4 = *(const float4*)(hb + kk);
                float4 w4 = *(const float4*)(wj + kk);
                a0 = fmaf(h4.x, w4.x, a0);
                a1 = fmaf(h4.y, w4.y, a1);
                a2 = fmaf(h4.z, w4.z, a2);
                a3 = fmaf(h4.w, w4.w, a3);
            }
            __syncthreads();
        }

        size_t row = (size_t)t * BB + b;
        float v = tanhf(((a0 + a1) + (a2 + a3)) + pre[row * HH + col] + bj);
        ys[row * HH + col] = v;
    }
}

// ---------------- online logsumexp per row ----------------
__global__ void lse_kernel(const float* __restrict__ logits, float* __restrict__ lse) {
    int r = blockIdx.x;
    int tid = threadIdx.x;
    const float* row = logits + (size_t)r * VV;
    float m = -1e30f, s = 0.f;
    for (int i = tid; i < VV; i += 256) {
        float x = row[i];
        if (x > m) { s = s * __expf(m - x) + 1.f; m = x; }
        else       { s += __expf(x - m); }
    }
    __shared__ float sm[256], ss[256];
    sm[tid] = m; ss[tid] = s;
    __syncthreads();
    for (int st = 128; st > 0; st >>= 1) {
        if (tid < st) {
            float m2 = sm[tid + st], s2 = ss[tid + st];
            float M = fmaxf(sm[tid], m2);
            ss[tid] = ss[tid] * __expf(sm[tid] - M) + s2 * __expf(m2 - M);
            sm[tid] = M;
        }
        __syncthreads();
    }
    if (tid == 0) lse[r] = sm[0] + logf(ss[0]);
}

__global__ void norm_kernel(float* __restrict__ out, const float* __restrict__ lse) {
    int r = blockIdx.y;
    int c = blockIdx.x * 256 + threadIdx.x;
    out[(size_t)r * VV + c] -= lse[r];
}

__global__ void hid_kernel(const float* __restrict__ ys0, const float* __restrict__ ys1,
                           float* __restrict__ out) {
    int i = blockIdx.x * 256 + threadIdx.x;
    int l = i >> 15;
    int rem = i & 32767;
    const float* src = l ? ys1 : ys0;
    out[i] = src[(size_t)(TT - 1) * BB * HH + rem];
}

// ---------------- launch ----------------
extern "C" void kernel_launch(void* const* d_in, const int* in_sizes, int n_in,
                              void* d_out, int out_size) {
    const int*   input_x = (const int*)d_in[0];
    const float* hidden  = (const float*)d_in[1];
    const float* emb     = (const float*)d_in[2];
    const float* W_ih    = (const float*)d_in[3];
    const float* W_hh    = (const float*)d_in[4];
    const float* b_ih    = (const float*)d_in[5];
    const float* b_hh    = (const float*)d_in[6];
    const float* W_out   = (const float*)d_in[7];
    const float* b_out   = (const float*)d_in[8];
    float* out = (float*)d_out;

    float *bufA, *bufB, *bufC, *lse;
    cudaGetSymbolAddress((void**)&bufA, g_bufA);
    cudaGetSymbolAddress((void**)&bufB, g_bufB);
    cudaGetSymbolAddress((void**)&bufC, g_bufC);
    cudaGetSymbolAddress((void**)&lse,  g_lse);

    static bool attr_done = false;
    if (!attr_done) {
        cudaFuncSetAttribute(persistent_rnn, cudaFuncAttributeMaxDynamicSharedMemorySize,
                             RNN_SMEM_BYTES);
        attr_done = true;
    }

    // x = emb[input] -> bufA [4096,1024]
    embed_kernel<<<NROWS, 256>>>(input_x, emb, bufA);

    // layer 0: pre = x @ Wih0^T + bih0 -> bufB ; recurrence -> bufC
    gemm_tf32<<<dim3(HH / GBN, NROWS / GBM), 256>>>(bufA, W_ih, b_ih, bufB, NROWS, HH, HH);
    reset_bar_kernel<<<1, 1>>>();
    persistent_rnn<<<RNN_BLOCKS, 256, RNN_SMEM_BYTES>>>(bufB, bufC, hidden, W_hh, b_hh);

    // layer 1: pre = ys0 @ Wih1^T + bih1 -> bufB ; recurrence -> bufA
    gemm_tf32<<<dim3(HH / GBN, NROWS / GBM), 256>>>(bufC, W_ih + (size_t)HH * HH, b_ih + HH,
                                                    bufB, NROWS, HH, HH);
    reset_bar_kernel<<<1, 1>>>();
    persistent_rnn<<<RNN_BLOCKS, 256, RNN_SMEM_BYTES>>>(bufB, bufA, hidden + BB * HH,
                                                        W_hh + (size_t)HH * HH, b_hh + HH);

    // logits = ys1 @ W_out^T + b_out -> d_out
    gemm_tf32<<<dim3(VV / GBN, NROWS / GBM), 256>>>(bufA, W_out, b_out, out, NROWS, VV, HH);

    lse_kernel<<<NROWS, 256>>>(out, lse);
    norm_kernel<<<dim3(VV / 256, NROWS), 256>>>(out, lse);

    if (out_size >= NROWS * VV + NLAYERS * BB * HH)
        hid_kernel<<<(NLAYERS * BB * HH) / 256, 256>>>(bufC, bufA, out + (size_t)NROWS * VV);
}